// round 12
// baseline (speedup 1.0000x reference)
#include <cuda_runtime.h>
#include <cuda_bf16.h>
#include <cstdint>

#define HH 16
#define SS 2048
#define DD 128
#define BM 64
#define BN 32
#define NT 128
#define NELEM (2 * HH * SS * DD)

// ---- device scratch: split K and transposed-split V (bf16 hi/lo) ----
__device__ __nv_bfloat16 g_Khi[NELEM];
__device__ __nv_bfloat16 g_Klo[NELEM];
__device__ __nv_bfloat16 g_VThi[NELEM];   // [bh][d][s]
__device__ __nv_bfloat16 g_VTlo[NELEM];

// ---- main-kernel smem layout (bytes) ----
#define OFF_AMCX 0                     // 2 bufs x (am 128B + cx 128B)
#define OFF_QHI  1024                  // 64 rows x 256B
#define OFF_QLO  17408
#define OFF_KV   33792                 // 2 bufs x 32KB: [KHI 8K][KLO 8K][VHI 8K][VLO 8K]
#define SMEM_TOTAL 99328               // 97KB -> 2 CTAs/SM

__device__ __forceinline__ uint32_t smem_u32(const void* p){
    uint32_t a;
    asm("{ .reg .u64 t; cvta.to.shared.u64 t, %1; cvt.u32.u64 %0, t; }" : "=r"(a) : "l"(p));
    return a;
}
__device__ __forceinline__ void split2(float x, float y, uint32_t& hi, uint32_t& lo){
    __nv_bfloat162 h = __floats2bfloat162_rn(x, y);
    __nv_bfloat162 l = __floats2bfloat162_rn(x - __bfloat162float(h.x), y - __bfloat162float(h.y));
    hi = *reinterpret_cast<uint32_t*>(&h);
    lo = *reinterpret_cast<uint32_t*>(&l);
}
__device__ __forceinline__ void mma_bf16(float* d, const uint32_t* a, uint32_t b0, uint32_t b1){
    asm("mma.sync.aligned.m16n8k16.row.col.f32.bf16.bf16.f32 "
        "{%0,%1,%2,%3}, {%4,%5,%6,%7}, {%8,%9}, {%0,%1,%2,%3};"
        : "+f"(d[0]), "+f"(d[1]), "+f"(d[2]), "+f"(d[3])
        : "r"(a[0]), "r"(a[1]), "r"(a[2]), "r"(a[3]), "r"(b0), "r"(b1));
}
__device__ __forceinline__ void ldsm4(uint32_t* r, uint32_t addr){
    asm("ldmatrix.sync.aligned.m8n8.x4.shared.b16 {%0,%1,%2,%3}, [%4];"
        : "=r"(r[0]), "=r"(r[1]), "=r"(r[2]), "=r"(r[3]) : "r"(addr) : "memory");
}
__device__ __forceinline__ void cpa16(uint32_t dst, const void* src){
    asm volatile("cp.async.cg.shared.global [%0], [%1], 16;" :: "r"(dst), "l"(src));
}
__device__ __forceinline__ void cpa8(uint32_t dst, const void* src){
    asm volatile("cp.async.ca.shared.global [%0], [%1], 8;" :: "r"(dst), "l"(src));
}
#define CP_COMMIT() asm volatile("cp.async.commit_group;" ::: "memory")
#define CP_WAIT0()  asm volatile("cp.async.wait_group 0;" ::: "memory")
#define CP_WAIT1()  asm volatile("cp.async.wait_group 1;" ::: "memory")

// =================== prepass kernels ===================
__global__ void prep_k_kernel(const float* __restrict__ K){
    size_t i = (size_t)blockIdx.x * 256 + threadIdx.x;   // float4 index
    float4 v = ((const float4*)K)[i];
    uint32_t h0, l0, h1, l1;
    split2(v.x, v.y, h0, l0);
    split2(v.z, v.w, h1, l1);
    ((uint2*)g_Khi)[i] = make_uint2(h0, h1);
    ((uint2*)g_Klo)[i] = make_uint2(l0, l1);
}
__global__ void prep_v_kernel(const float* __restrict__ V){
    __shared__ float ts[32][33];
    const int bh = blockIdx.z, d0 = blockIdx.y * 32, s0 = blockIdx.x * 32;
    const int t = threadIdx.x, i = t >> 3, j4 = (t & 7) * 4;
    const float* Vp = V + ((size_t)bh * SS + s0) * DD + d0;
    float4 v = *(const float4*)(Vp + (size_t)i * DD + j4);
    ts[i][j4] = v.x; ts[i][j4 + 1] = v.y; ts[i][j4 + 2] = v.z; ts[i][j4 + 3] = v.w;
    __syncthreads();
    float a = ts[j4][i], b = ts[j4 + 1][i], c = ts[j4 + 2][i], d = ts[j4 + 3][i];
    uint32_t h0, l0, h1, l1;
    split2(a, b, h0, l0);
    split2(c, d, h1, l1);
    size_t dst = ((size_t)bh * DD + d0 + i) * SS + s0 + j4;
    *(uint2*)(g_VThi + dst) = make_uint2(h0, h1);
    *(uint2*)(g_VTlo + dst) = make_uint2(l0, l1);
}

// =================== main kernel ===================
// Stream one 32-key K/V/am/ctx tile into ring buffer `buf`.
__device__ __forceinline__ void issue_loads(const __nv_bfloat16* Khb, const __nv_bfloat16* Klb,
                                            const __nv_bfloat16* Vhb, const __nv_bfloat16* Vlb,
                                            const float* AM, const float* CTX, size_t bS,
                                            int kbase, int buf, uint32_t sb, int tid)
{
    const uint32_t kv = sb + OFF_KV + (uint32_t)buf * 32768u;
    #pragma unroll
    for (int i = 0; i < 4; ++i){                      // K: 32 rows x 16 chunks
        int flat = tid + i * NT;
        int r = flat >> 4, c = flat & 15;
        uint32_t o = (uint32_t)r * 256u + ((((uint32_t)c) ^ ((uint32_t)r & 7u)) << 4);
        cpa16(kv + o,         (const char*)(Khb + (size_t)(kbase + r) * DD) + c * 16);
        cpa16(kv + 8192u + o, (const char*)(Klb + (size_t)(kbase + r) * DD) + c * 16);
    }
    #pragma unroll
    for (int i = 0; i < 4; ++i){                      // VT: 128 rows x 4 chunks (64B rows)
        int flat = tid + i * NT;
        int d = flat >> 2, c = flat & 3;
        uint32_t o = (uint32_t)d * 64u + ((((uint32_t)c) ^ (((uint32_t)d >> 1) & 3u)) << 4);
        cpa16(kv + 16384u + o, (const char*)(Vhb + (size_t)d * SS + kbase) + c * 16);
        cpa16(kv + 24576u + o, (const char*)(Vlb + (size_t)d * SS + kbase) + c * 16);
    }
    if (tid < 16)       cpa8(sb + OFF_AMCX + buf * 256 + tid * 8,              AM  + bS + kbase + 2 * tid);
    else if (tid < 32)  cpa8(sb + OFF_AMCX + buf * 256 + 128 + (tid - 16) * 8, CTX + bS + kbase + 2 * (tid - 16));
    CP_COMMIT();
}

__global__ __launch_bounds__(NT, 2)
void attn_hmma_kernel(const float* __restrict__ Q,
                      const float* __restrict__ AM,
                      const float* __restrict__ HM,
                      const float* __restrict__ CTX,
                      float* __restrict__ out)
{
    extern __shared__ char sm[];
    const uint32_t sb = smem_u32(sm);
    const int tid = threadIdx.x, wid = tid >> 5, lane = tid & 31;

    const int it = (gridDim.x - 1) - blockIdx.x;   // heavy q-tiles first
    const int h = blockIdx.y, b = blockIdx.z;
    const int bh = b * HH + h;
    const int q0 = it * BM;
    const int nt = 2 * (it + 1);                   // 32-key tiles

    const float* Qp = Q + ((size_t)bh * SS + q0) * DD;
    const __nv_bfloat16* Khb = g_Khi  + (size_t)bh * SS * DD;
    const __nv_bfloat16* Klb = g_Klo  + (size_t)bh * SS * DD;
    const __nv_bfloat16* Vhb = g_VThi + (size_t)bh * SS * DD;
    const __nv_bfloat16* Vlb = g_VTlo + (size_t)bh * SS * DD;
    const size_t bS = (size_t)b * SS;

    // ---- prologue: start tile-0 streaming, overlap with Q load+split ----
    issue_loads(Khb, Klb, Vhb, Vlb, AM, CTX, bS, 0, 0, sb, tid);
    {
        const float4* Qg = (const float4*)Qp;
        #pragma unroll
        for (int i = 0; i < 16; ++i){
            int flat = tid + i * NT;               // 0..2047
            int r = flat >> 5, g = flat & 31;
            float4 v = Qg[flat];
            uint32_t h0, l0, h1, l1;
            split2(v.x, v.y, h0, l0);
            split2(v.z, v.w, h1, l1);
            uint32_t o = (uint32_t)r * 256u
                       + ((((uint32_t)(g >> 1)) ^ ((uint32_t)r & 7u)) << 4)
                       + (((uint32_t)(g & 1)) << 3);
            *(uint2*)(sm + OFF_QHI + o) = make_uint2(h0, h1);
            *(uint2*)(sm + OFF_QLO + o) = make_uint2(l0, l1);
        }
    }

    const int rowA = 16 * wid + (lane & 15);
    const uint32_t qbh = sb + OFF_QHI + rowA * 256;
    const uint32_t qbl = sb + OFF_QLO + rowA * 256;
    const uint32_t swA = rowA & 7, hi4 = lane >> 4;
    const int rB  = (lane & 7) + ((lane >> 4) & 1) * 8;
    const uint32_t cof = (lane >> 3) & 1;

    const int g    = lane >> 2;
    const int colt = 2 * (lane & 3);
    const int qg0 = q0 + 16 * wid + g;
    const int qg1 = qg0 + 8;

    __syncthreads();   // Q smem visible

    // ---- persistent Q fragments (hi/lo), loaded once ----
    uint32_t qh[8][4], ql[8][4];
    #pragma unroll
    for (int kb = 0; kb < 8; ++kb){
        uint32_t coff = (((uint32_t)(2 * kb) + hi4) ^ swA) << 4;
        ldsm4(qh[kb], qbh + coff);
        ldsm4(ql[kb], qbl + coff);
    }

    float oacc[16][4];
    #pragma unroll
    for (int i = 0; i < 16; ++i)
        #pragma unroll
        for (int j = 0; j < 4; ++j) oacc[i][j] = 0.f;
    float z0t = 0.f, z1t = 0.f;

    for (int jt = 0; jt < nt; ++jt){
        const int kbase = jt * BN;
        const int cur = jt & 1;
        const uint32_t kvb = sb + OFF_KV + (uint32_t)cur * 32768u;

        __syncthreads();      // all warps done reading buf cur^1 (tile jt-1)
        if (jt + 1 < nt){
            issue_loads(Khb, Klb, Vhb, Vlb, AM, CTX, bS, (jt + 1) * BN, cur ^ 1, sb, tid);
            CP_WAIT1();       // tile jt complete (jt+1 may stay in flight)
        } else {
            CP_WAIT0();
        }
        __syncthreads();      // tile jt visible to all threads

        // causal skip: last k-tile fully masked for warps 0-1 (rows < kbase)
        if (jt == nt - 1 && wid < 2) continue;

        const float* amb = (const float*)(sm + OFF_AMCX + cur * 256);
        const float* cxb = amb + 32;

        // ---- S = Q K^T : Q from registers, 96 MMA ----
        float sacc[4][4];
        #pragma unroll
        for (int i = 0; i < 4; ++i)
            #pragma unroll
            for (int j = 0; j < 4; ++j) sacc[i][j] = 0.f;

        #pragma unroll
        for (int kb = 0; kb < 8; ++kb){
            uint32_t bh4[2][4], bl4[2][4];
            #pragma unroll
            for (int np = 0; np < 2; ++np){
                int rowB = 16 * np + rB;
                uint32_t ko = (uint32_t)rowB * 256u
                            + ((((uint32_t)(2 * kb) + cof) ^ ((uint32_t)rowB & 7u)) << 4);
                ldsm4(bh4[np], kvb + ko);
                ldsm4(bl4[np], kvb + 8192u + ko);
            }
            #pragma unroll
            for (int np = 0; np < 2; ++np){            // hi x hi
                mma_bf16(sacc[2 * np],     qh[kb], bh4[np][0], bh4[np][1]);
                mma_bf16(sacc[2 * np + 1], qh[kb], bh4[np][2], bh4[np][3]);
            }
            #pragma unroll
            for (int np = 0; np < 2; ++np){            // hi x lo
                mma_bf16(sacc[2 * np],     qh[kb], bl4[np][0], bl4[np][1]);
                mma_bf16(sacc[2 * np + 1], qh[kb], bl4[np][2], bl4[np][3]);
            }
            #pragma unroll
            for (int np = 0; np < 2; ++np){            // lo x hi
                mma_bf16(sacc[2 * np],     ql[kb], bh4[np][0], bh4[np][1]);
                mma_bf16(sacc[2 * np + 1], ql[kb], bh4[np][2], bh4[np][3]);
            }
        }

        // ---- softmax (m=0): p = exp(s+am), causal zeroing; P -> bf16 hi/lo frags ----
        uint32_t PH[4][2], PL[4][2];
        #pragma unroll
        for (int j = 0; j < 4; ++j){
            int col = kbase + 8 * j + colt;
            float2 am2 = *(const float2*)&amb[8 * j + colt];
            float2 cx2 = *(const float2*)&cxb[8 * j + colt];
            float p0 = (col     <= qg0) ? __expf(sacc[j][0] + am2.x) : 0.f;
            float p1 = (col + 1 <= qg0) ? __expf(sacc[j][1] + am2.y) : 0.f;
            float p2 = (col     <= qg1) ? __expf(sacc[j][2] + am2.x) : 0.f;
            float p3 = (col + 1 <= qg1) ? __expf(sacc[j][3] + am2.y) : 0.f;
            z0t += p0 + p1;  z1t += p2 + p3;          // Z uses UNSCALED p
            p0 *= cx2.x; p1 *= cx2.y;                 // ctx applied post-softmax
            p2 *= cx2.x; p3 *= cx2.y;
            split2(p0, p1, PH[j][0], PL[j][0]);
            split2(p2, p3, PH[j][1], PL[j][1]);
        }

        // ---- O += P V : 96 MMA ----
        #pragma unroll
        for (int kb = 0; kb < 2; ++kb){
            uint32_t Ahf[4] = {PH[2 * kb][0], PH[2 * kb][1], PH[2 * kb + 1][0], PH[2 * kb + 1][1]};
            uint32_t Alf[4] = {PL[2 * kb][0], PL[2 * kb][1], PL[2 * kb + 1][0], PL[2 * kb + 1][1]};
            #pragma unroll
            for (int hg = 0; hg < 2; ++hg){
                uint32_t vh[4][4], vl[4][4];
                #pragma unroll
                for (int q = 0; q < 4; ++q){
                    int rowV = 16 * (4 * hg + q) + rB;
                    uint32_t vo = (uint32_t)rowV * 64u
                                + ((((uint32_t)(2 * kb) + cof) ^ (((uint32_t)rowV >> 1) & 3u)) << 4);
                    ldsm4(vh[q], kvb + 16384u + vo);
                    ldsm4(vl[q], kvb + 24576u + vo);
                }
                #pragma unroll
                for (int q = 0; q < 4; ++q){           // Ph x Vh
                    int np = 4 * hg + q;
                    mma_bf16(oacc[2 * np],     Ahf, vh[q][0], vh[q][1]);
                    mma_bf16(oacc[2 * np + 1], Ahf, vh[q][2], vh[q][3]);
                }
                #pragma unroll
                for (int q = 0; q < 4; ++q){           // Ph x Vl
                    int np = 4 * hg + q;
                    mma_bf16(oacc[2 * np],     Ahf, vl[q][0], vl[q][1]);
                    mma_bf16(oacc[2 * np + 1], Ahf, vl[q][2], vl[q][3]);
                }
                #pragma unroll
                for (int q = 0; q < 4; ++q){           // Pl x Vh
                    int np = 4 * hg + q;
                    mma_bf16(oacc[2 * np],     Alf, vh[q][0], vh[q][1]);
                    mma_bf16(oacc[2 * np + 1], Alf, vh[q][2], vh[q][3]);
                }
            }
        }
    }

    // ---- epilogue: reduce Z across lane quads, /Z, * head_mask, store ----
    z0t += __shfl_xor_sync(0xffffffffu, z0t, 1);
    z0t += __shfl_xor_sync(0xffffffffu, z0t, 2);
    z1t += __shfl_xor_sync(0xffffffffu, z1t, 1);
    z1t += __shfl_xor_sync(0xffffffffu, z1t, 2);

    const float hm = HM[h];
    const float i0 = hm / z0t, i1 = hm / z1t;
    float* O0 = out + ((size_t)bh * SS + q0 + 16 * wid + g) * DD;
    float* O1 = O0 + 8 * DD;
    #pragma unroll
    for (int nb = 0; nb < 16; ++nb){
        *(float2*)&O0[8 * nb + colt] = make_float2(oacc[nb][0] * i0, oacc[nb][1] * i0);
        *(float2*)&O1[8 * nb + colt] = make_float2(oacc[nb][2] * i1, oacc[nb][3] * i1);
    }
}

extern "C" void kernel_launch(void* const* d_in, const int* in_sizes, int n_in,
                              void* d_out, int out_size)
{
    (void)in_sizes; (void)n_in; (void)out_size;
    const float* Q   = (const float*)d_in[0];
    const float* K   = (const float*)d_in[1];
    const float* V   = (const float*)d_in[2];
    const float* AM  = (const float*)d_in[3];
    const float* HM  = (const float*)d_in[4];
    const float* CTX = (const float*)d_in[5];
    float* out = (float*)d_out;

    cudaFuncSetAttribute(attn_hmma_kernel,
                         cudaFuncAttributeMaxDynamicSharedMemorySize, SMEM_TOTAL);

    prep_k_kernel<<<NELEM / 4 / 256, 256>>>(K);
    prep_v_kernel<<<dim3(SS / 32, DD / 32, 2 * HH), 256>>>(V);

    dim3 grid(SS / BM, HH, 2);
    attn_hmma_kernel<<<grid, NT, SMEM_TOTAL>>>(Q, AM, HM, CTX, out);
}

// round 14
// speedup vs baseline: 1.0028x; 1.0028x over previous
#include <cuda_runtime.h>
#include <cuda_bf16.h>
#include <cstdint>

#define HH 16
#define SS 2048
#define DD 128
#define BM 128
#define BN 64
#define NT 256
#define NELEM (2 * HH * SS * DD)

// ---- device scratch: split K and transposed-split V (bf16 hi/lo) ----
__device__ __nv_bfloat16 g_Khi[NELEM];
__device__ __nv_bfloat16 g_Klo[NELEM];
__device__ __nv_bfloat16 g_VThi[NELEM];   // [bh][d][s]
__device__ __nv_bfloat16 g_VTlo[NELEM];

// ---- main-kernel smem layout (bytes) ----
#define OFF_AMCX 0                     // 2 bufs x (am 256B + cx 256B)
#define OFF_QHI  1024                  // 128 rows x 256B
#define OFF_QLO  33792
#define OFF_KV   66560                 // 2 bufs x 64KB: [KHI 16K][KLO 16K][VHI 16K][VLO 16K]
#define SMEM_TOTAL 197632

__device__ __forceinline__ uint32_t smem_u32(const void* p){
    uint32_t a;
    asm("{ .reg .u64 t; cvta.to.shared.u64 t, %1; cvt.u32.u64 %0, t; }" : "=r"(a) : "l"(p));
    return a;
}
__device__ __forceinline__ void split2(float x, float y, uint32_t& hi, uint32_t& lo){
    __nv_bfloat162 h = __floats2bfloat162_rn(x, y);
    __nv_bfloat162 l = __floats2bfloat162_rn(x - __bfloat162float(h.x), y - __bfloat162float(h.y));
    hi = *reinterpret_cast<uint32_t*>(&h);
    lo = *reinterpret_cast<uint32_t*>(&l);
}
__device__ __forceinline__ void mma_bf16(float* d, const uint32_t* a, uint32_t b0, uint32_t b1){
    asm("mma.sync.aligned.m16n8k16.row.col.f32.bf16.bf16.f32 "
        "{%0,%1,%2,%3}, {%4,%5,%6,%7}, {%8,%9}, {%0,%1,%2,%3};"
        : "+f"(d[0]), "+f"(d[1]), "+f"(d[2]), "+f"(d[3])
        : "r"(a[0]), "r"(a[1]), "r"(a[2]), "r"(a[3]), "r"(b0), "r"(b1));
}
// ldmatrix: volatile (ordered vs other volatile asm = cp.async waits, and vs
// __syncthreads) but NO "memory" clobber — softmax math and non-aliasing smem
// loads (amb/cxb) may be interleaved into the ldsm+mma stream by the compiler.
__device__ __forceinline__ void ldsm4(uint32_t* r, uint32_t addr){
    asm volatile("ldmatrix.sync.aligned.m8n8.x4.shared.b16 {%0,%1,%2,%3}, [%4];"
        : "=r"(r[0]), "=r"(r[1]), "=r"(r[2]), "=r"(r[3]) : "r"(addr));
}
__device__ __forceinline__ void cpa16(uint32_t dst, const void* src){
    asm volatile("cp.async.cg.shared.global [%0], [%1], 16;" :: "r"(dst), "l"(src));
}
__device__ __forceinline__ void cpa8(uint32_t dst, const void* src){
    asm volatile("cp.async.ca.shared.global [%0], [%1], 8;" :: "r"(dst), "l"(src));
}
#define CP_COMMIT() asm volatile("cp.async.commit_group;" ::: "memory")
#define CP_WAIT0()  asm volatile("cp.async.wait_group 0;" ::: "memory")
#define CP_WAIT1()  asm volatile("cp.async.wait_group 1;" ::: "memory")

// =================== prepass kernels ===================
__global__ void prep_k_kernel(const float* __restrict__ K){
    size_t i = (size_t)blockIdx.x * 256 + threadIdx.x;   // float4 index
    float4 v = ((const float4*)K)[i];
    uint32_t h0, l0, h1, l1;
    split2(v.x, v.y, h0, l0);
    split2(v.z, v.w, h1, l1);
    ((uint2*)g_Khi)[i] = make_uint2(h0, h1);
    ((uint2*)g_Klo)[i] = make_uint2(l0, l1);
}
__global__ void prep_v_kernel(const float* __restrict__ V){
    __shared__ float ts[32][33];
    const int bh = blockIdx.z, d0 = blockIdx.y * 32, s0 = blockIdx.x * 32;
    const int t = threadIdx.x, i = t >> 3, j4 = (t & 7) * 4;
    const float* Vp = V + ((size_t)bh * SS + s0) * DD + d0;
    float4 v = *(const float4*)(Vp + (size_t)i * DD + j4);
    ts[i][j4] = v.x; ts[i][j4 + 1] = v.y; ts[i][j4 + 2] = v.z; ts[i][j4 + 3] = v.w;
    __syncthreads();
    float a = ts[j4][i], b = ts[j4 + 1][i], c = ts[j4 + 2][i], d = ts[j4 + 3][i];
    uint32_t h0, l0, h1, l1;
    split2(a, b, h0, l0);
    split2(c, d, h1, l1);
    size_t dst = ((size_t)bh * DD + d0 + i) * SS + s0 + j4;
    *(uint2*)(g_VThi + dst) = make_uint2(h0, h1);
    *(uint2*)(g_VTlo + dst) = make_uint2(l0, l1);
}

// =================== main kernel helpers ===================
__device__ __forceinline__ void issue_loads(const __nv_bfloat16* Khb, const __nv_bfloat16* Klb,
                                            const __nv_bfloat16* Vhb, const __nv_bfloat16* Vlb,
                                            const float* AM, const float* CTX, size_t bS,
                                            int kbase, int buf, uint32_t sb, int tid)
{
    const uint32_t kv = sb + OFF_KV + (uint32_t)buf * 65536u;
    #pragma unroll
    for (int i = 0; i < 4; ++i){                      // K: 64 rows x 16 chunks
        int flat = tid + i * NT;
        int r = flat >> 4, c = flat & 15;
        uint32_t o = (uint32_t)r * 256u + ((((uint32_t)c) ^ ((uint32_t)r & 7u)) << 4);
        cpa16(kv + o,          (const char*)(Khb + (size_t)(kbase + r) * DD) + c * 16);
        cpa16(kv + 16384u + o, (const char*)(Klb + (size_t)(kbase + r) * DD) + c * 16);
    }
    #pragma unroll
    for (int i = 0; i < 4; ++i){                      // VT: 128 rows x 8 chunks
        int flat = tid + i * NT;
        int d = flat >> 3, c = flat & 7;
        uint32_t o = (uint32_t)d * 128u + ((((uint32_t)c) ^ ((uint32_t)d & 7u)) << 4);
        cpa16(kv + 32768u + o, (const char*)(Vhb + (size_t)d * SS + kbase) + c * 16);
        cpa16(kv + 49152u + o, (const char*)(Vlb + (size_t)d * SS + kbase) + c * 16);
    }
    if (tid < 32)       cpa8(sb + OFF_AMCX + buf * 512 + tid * 8,              AM  + bS + kbase + 2 * tid);
    else if (tid < 64)  cpa8(sb + OFF_AMCX + buf * 512 + 256 + (tid - 32) * 8, CTX + bS + kbase + 2 * (tid - 32));
    CP_COMMIT();
}

// QK for 2 key-blocks (np0, np0+1): fills the passed 4-accumulator slice
__device__ __forceinline__ void qk_half(float (*sacc)[4], uint32_t qbh, uint32_t qbl,
                                        uint32_t kvb, int np0, uint32_t swA, uint32_t hi4,
                                        int rB, uint32_t cof)
{
    #pragma unroll
    for (int kb = 0; kb < 8; ++kb){
        uint32_t ah[4], al[4];
        uint32_t coff = (((uint32_t)(2 * kb) + hi4) ^ swA) << 4;
        ldsm4(ah, qbh + coff);
        ldsm4(al, qbl + coff);
        uint32_t bh4[2][4], bl4[2][4];
        #pragma unroll
        for (int q = 0; q < 2; ++q){
            int rowB = 16 * (np0 + q) + rB;
            uint32_t ko = (uint32_t)rowB * 256u
                        + ((((uint32_t)(2 * kb) + cof) ^ ((uint32_t)rowB & 7u)) << 4);
            ldsm4(bh4[q], kvb + ko);
            ldsm4(bl4[q], kvb + 16384u + ko);
        }
        #pragma unroll
        for (int q = 0; q < 2; ++q){               // hi x hi
            mma_bf16(sacc[2 * q],     ah, bh4[q][0], bh4[q][1]);
            mma_bf16(sacc[2 * q + 1], ah, bh4[q][2], bh4[q][3]);
        }
        #pragma unroll
        for (int q = 0; q < 2; ++q){               // hi x lo
            mma_bf16(sacc[2 * q],     ah, bl4[q][0], bl4[q][1]);
            mma_bf16(sacc[2 * q + 1], ah, bl4[q][2], bl4[q][3]);
        }
        #pragma unroll
        for (int q = 0; q < 2; ++q){               // lo x hi
            mma_bf16(sacc[2 * q],     al, bh4[q][0], bh4[q][1]);
            mma_bf16(sacc[2 * q + 1], al, bh4[q][2], bh4[q][3]);
        }
    }
}

// softmax for j in [j0, j0+4): sacc slice -> PH/PL slice; z accumulated per-thread
__device__ __forceinline__ void softmax_half(const float (*sacc)[4], uint32_t (*PH)[2], uint32_t (*PL)[2],
                                             const float* amb, const float* cxb, int j0,
                                             int kbase, int colt, int qg0, int qg1,
                                             float& z0t, float& z1t)
{
    #pragma unroll
    for (int jj = 0; jj < 4; ++jj){
        int j = j0 + jj;
        int col = kbase + 8 * j + colt;
        float2 am2 = *(const float2*)&amb[8 * j + colt];
        float2 cx2 = *(const float2*)&cxb[8 * j + colt];
        float p0 = (col     <= qg0) ? __expf(sacc[jj][0] + am2.x) : 0.f;
        float p1 = (col + 1 <= qg0) ? __expf(sacc[jj][1] + am2.y) : 0.f;
        float p2 = (col     <= qg1) ? __expf(sacc[jj][2] + am2.x) : 0.f;
        float p3 = (col + 1 <= qg1) ? __expf(sacc[jj][3] + am2.y) : 0.f;
        z0t += p0 + p1;  z1t += p2 + p3;          // Z uses UNSCALED p (reduced at epilogue)
        p0 *= cx2.x; p1 *= cx2.y;                 // ctx applied post-softmax
        p2 *= cx2.x; p3 *= cx2.y;
        split2(p0, p1, PH[jj][0], PL[jj][0]);
        split2(p2, p3, PH[jj][1], PL[jj][1]);
    }
}

// PV for kb in [kb0, kb0+2): needs PH/PL[2kb..2kb+1]
__device__ __forceinline__ void pv_half(float (*oacc)[4], const uint32_t (*PH)[2], const uint32_t (*PL)[2],
                                        uint32_t kvb, int kb0, int rB, uint32_t cof)
{
    #pragma unroll
    for (int k2 = 0; k2 < 2; ++k2){
        int kb = kb0 + k2;
        uint32_t Ahf[4] = {PH[2 * k2][0], PH[2 * k2][1], PH[2 * k2 + 1][0], PH[2 * k2 + 1][1]};
        uint32_t Alf[4] = {PL[2 * k2][0], PL[2 * k2][1], PL[2 * k2 + 1][0], PL[2 * k2 + 1][1]};
        #pragma unroll
        for (int hg = 0; hg < 2; ++hg){
            uint32_t vh[4][4], vl[4][4];
            #pragma unroll
            for (int q = 0; q < 4; ++q){
                int rowV = 16 * (4 * hg + q) + rB;
                uint32_t vo = (uint32_t)rowV * 128u
                            + ((((uint32_t)(2 * kb) + cof) ^ ((uint32_t)rowV & 7u)) << 4);
                ldsm4(vh[q], kvb + 32768u + vo);
                ldsm4(vl[q], kvb + 49152u + vo);
            }
            #pragma unroll
            for (int q = 0; q < 4; ++q){           // Ph x Vh
                int np = 4 * hg + q;
                mma_bf16(oacc[2 * np],     Ahf, vh[q][0], vh[q][1]);
                mma_bf16(oacc[2 * np + 1], Ahf, vh[q][2], vh[q][3]);
            }
            #pragma unroll
            for (int q = 0; q < 4; ++q){           // Ph x Vl
                int np = 4 * hg + q;
                mma_bf16(oacc[2 * np],     Ahf, vl[q][0], vl[q][1]);
                mma_bf16(oacc[2 * np + 1], Ahf, vl[q][2], vl[q][3]);
            }
            #pragma unroll
            for (int q = 0; q < 4; ++q){           // Pl x Vh
                int np = 4 * hg + q;
                mma_bf16(oacc[2 * np],     Alf, vh[q][0], vh[q][1]);
                mma_bf16(oacc[2 * np + 1], Alf, vh[q][2], vh[q][3]);
            }
        }
    }
}

__global__ __launch_bounds__(NT, 1)
void attn_hmma_kernel(const float* __restrict__ Q,
                      const float* __restrict__ AM,
                      const float* __restrict__ HM,
                      const float* __restrict__ CTX,
                      float* __restrict__ out)
{
    extern __shared__ char sm[];
    const uint32_t sb = smem_u32(sm);
    const int tid = threadIdx.x, wid = tid >> 5, lane = tid & 31;

    const int it = (gridDim.x - 1) - blockIdx.x;   // heavy q-tiles first
    const int h = blockIdx.y, b = blockIdx.z;
    const int bh = b * HH + h;
    const int q0 = it * BM;
    const int nt = 2 * (it + 1);

    const float* Qp = Q + ((size_t)bh * SS + q0) * DD;
    const __nv_bfloat16* Khb = g_Khi  + (size_t)bh * SS * DD;
    const __nv_bfloat16* Klb = g_Klo  + (size_t)bh * SS * DD;
    const __nv_bfloat16* Vhb = g_VThi + (size_t)bh * SS * DD;
    const __nv_bfloat16* Vlb = g_VTlo + (size_t)bh * SS * DD;
    const size_t bS = (size_t)b * SS;

    // ---- prologue: start tile-0 streaming, overlap with Q load+split ----
    issue_loads(Khb, Klb, Vhb, Vlb, AM, CTX, bS, 0, 0, sb, tid);
    {
        const float4* Qg = (const float4*)Qp;
        #pragma unroll
        for (int i = 0; i < 16; ++i){
            int flat = tid + i * NT;
            int r = flat >> 5, g = flat & 31;
            float4 v = Qg[flat];
            uint32_t h0, l0, h1, l1;
            split2(v.x, v.y, h0, l0);
            split2(v.z, v.w, h1, l1);
            uint32_t o = (uint32_t)r * 256u
                       + ((((uint32_t)(g >> 1)) ^ ((uint32_t)r & 7u)) << 4)
                       + (((uint32_t)(g & 1)) << 3);
            *(uint2*)(sm + OFF_QHI + o) = make_uint2(h0, h1);
            *(uint2*)(sm + OFF_QLO + o) = make_uint2(l0, l1);
        }
    }

    const int rowA = 16 * wid + (lane & 15);
    const uint32_t qbh = sb + OFF_QHI + rowA * 256;
    const uint32_t qbl = sb + OFF_QLO + rowA * 256;
    const uint32_t swA = rowA & 7, hi4 = lane >> 4;
    const int rB  = (lane & 7) + ((lane >> 4) & 1) * 8;
    const uint32_t cof = (lane >> 3) & 1;

    const int g    = lane >> 2;
    const int colt = 2 * (lane & 3);
    const int qg0 = q0 + 16 * wid + g;
    const int qg1 = qg0 + 8;

    float oacc[16][4];
    #pragma unroll
    for (int i = 0; i < 16; ++i)
        #pragma unroll
        for (int j = 0; j < 4; ++j) oacc[i][j] = 0.f;
    float z0t = 0.f, z1t = 0.f;

    for (int jt = 0; jt < nt; ++jt){
        const int kbase = jt * BN;
        const int cur = jt & 1;
        const uint32_t kvb = sb + OFF_KV + (uint32_t)cur * 65536u;

        __syncthreads();      // all warps done reading buf cur^1 (tile jt-1)
        if (jt + 1 < nt){
            issue_loads(Khb, Klb, Vhb, Vlb, AM, CTX, bS, (jt + 1) * BN, cur ^ 1, sb, tid);
            CP_WAIT1();       // tile jt complete (jt+1 may stay in flight)
        } else {
            CP_WAIT0();
        }
        __syncthreads();      // tile jt visible to all threads

        // causal skip: last k-tile fully masked for warps 0-3 (rows < kbase)
        if (jt == nt - 1 && wid < 4) continue;

        const float* amb = (const float*)(sm + OFF_AMCX + cur * 512);
        const float* cxb = amb + 64;

        float sacc[8][4];
        #pragma unroll
        for (int i = 0; i < 8; ++i)
            #pragma unroll
            for (int j = 0; j < 4; ++j) sacc[i][j] = 0.f;

        uint32_t PH[8][2], PL[8][2];

        // Halved schedule: sm_h1 interleaves under QK_h2; sm_h2 under PV_h1.
        qk_half(sacc,     qbh, qbl, kvb, 0, swA, hi4, rB, cof);
        qk_half(sacc + 4, qbh, qbl, kvb, 2, swA, hi4, rB, cof);
        softmax_half(sacc,     PH,     PL,     amb, cxb, 0, kbase, colt, qg0, qg1, z0t, z1t);
        softmax_half(sacc + 4, PH + 4, PL + 4, amb, cxb, 4, kbase, colt, qg0, qg1, z0t, z1t);
        pv_half(oacc, PH,     PL,     kvb, 0, rB, cof);
        pv_half(oacc, PH + 4, PL + 4, kvb, 2, rB, cof);
    }

    // ---- epilogue: reduce Z across lane quads, /Z, * head_mask, store ----
    z0t += __shfl_xor_sync(0xffffffffu, z0t, 1);
    z0t += __shfl_xor_sync(0xffffffffu, z0t, 2);
    z1t += __shfl_xor_sync(0xffffffffu, z1t, 1);
    z1t += __shfl_xor_sync(0xffffffffu, z1t, 2);

    const float hm = HM[h];
    const float i0 = hm / z0t, i1 = hm / z1t;
    float* O0 = out + ((size_t)bh * SS + q0 + 16 * wid + g) * DD;
    float* O1 = O0 + 8 * DD;
    #pragma unroll
    for (int nb = 0; nb < 16; ++nb){
        *(float2*)&O0[8 * nb + colt] = make_float2(oacc[nb][0] * i0, oacc[nb][1] * i0);
        *(float2*)&O1[8 * nb + colt] = make_float2(oacc[nb][2] * i1, oacc[nb][3] * i1);
    }
}

extern "C" void kernel_launch(void* const* d_in, const int* in_sizes, int n_in,
                              void* d_out, int out_size)
{
    (void)in_sizes; (void)n_in; (void)out_size;
    const float* Q   = (const float*)d_in[0];
    const float* K   = (const float*)d_in[1];
    const float* V   = (const float*)d_in[2];
    const float* AM  = (const float*)d_in[3];
    const float* HM  = (const float*)d_in[4];
    const float* CTX = (const float*)d_in[5];
    float* out = (float*)d_out;

    cudaFuncSetAttribute(attn_hmma_kernel,
                         cudaFuncAttributeMaxDynamicSharedMemorySize, SMEM_TOTAL);

    prep_k_kernel<<<NELEM / 4 / 256, 256>>>(K);
    prep_v_kernel<<<dim3(SS / 32, DD / 32, 2 * HH), 256>>>(V);

    dim3 grid(SS / BM, HH, 2);
    attn_hmma_kernel<<<grid, NT, SMEM_TOTAL>>>(Q, AM, HM, CTX, out);
}